// round 6
// baseline (speedup 1.0000x reference)
#include <cuda_runtime.h>
#include <math.h>
#include <stdint.h>

// Problem constants
#define B_   8
#define P_   16384
#define M_   16
#define CI_  16
#define CO_  32
#define W_   17
#define OSTRIDE 288       // floats per output row in Wf (17 w-slots + residual)
#define WWM  24           // per-m stride in ww_s (2 wp-halves of 12, 16B aligned)
#define WARP_SM 400       // per-warp smem floats: ww 16*24=384 + nb 16

typedef unsigned long long ull;

// packed f32x2 (SASS FFMA2) — only reachable via PTX
#define FMA_F32X2(d, a, b, c) \
    asm("fma.rn.f32x2 %0, %1, %2, %3;" : "=l"(d) : "l"(a), "l"(b), "l"(c))
#define MUL_F32X2(d, a, b) \
    asm("mul.rn.f32x2 %0, %1, %2;" : "=l"(d) : "l"(a), "l"(b))
#define PACK_REPL_F32X2(out, s) \
    asm("mov.b64 %0, {%1, %1};" : "=l"(out) : "r"(s))
#define UNPACK_F32X2(lo, hi, in) \
    asm("mov.b64 {%0, %1}, %2;" : "=r"(lo), "=r"(hi) : "l"(in))

// smem (floats): Wf [32][288] = 9216 ; per-warp (4): ww[16][24] + nb[16] = 400
// total = 9216 + 1600 = 10816 floats = 43264 bytes

__global__ void __launch_bounds__(128, 4)
fused_conv_kernel(const float* __restrict__ in_pc,
                  const float* __restrict__ weights,
                  const float* __restrict__ bias,
                  const float* __restrict__ w_weights,
                  const float* __restrict__ weight_res,
                  const int*   __restrict__ neighbor_id,
                  float*       __restrict__ out)
{
    constexpr float SQ_CONV = 0.70710678118654752440f;
    constexpr float SQ_RES  = 0.70710678118654752440f;

    extern __shared__ float sm[];
    float* Wf = sm;                                   // [32][288]

    const int tid  = threadIdx.x;
    const int warp = tid >> 5;
    const int lane = tid & 31;

    float* ww_s = sm + 32 * OSTRIDE + warp * WARP_SM; // [16][24]
    int*   nb_s = (int*)(ww_s + 384);                 // [16]

    // ---- stage weights: Wf[o][w*16+i], col 272.. holds weight_res ----
    for (int idx = tid; idx < W_ * 512; idx += 128) {
        int w   = idx >> 9;
        int rem = idx & 511;
        int o   = rem >> 4;
        int i   = rem & 15;
        Wf[o * OSTRIDE + w * 16 + i] = weights[idx];
    }
    for (int idx = tid; idx < 512; idx += 128) {
        int o = idx >> 4, i = idx & 15;
        Wf[o * OSTRIDE + 272 + i] = weight_res[idx];
    }

    const int p = blockIdx.x * 4 + warp;

    // ---- per-warp staging: neighbor ids, masked ww (parity-split layout) ----
    if (lane < 16) {
        nb_s[lane] = neighbor_id[p * M_ + lane];
        ww_s[lane * WWM + 12 + 8] = 0.0f;     // wp1 slot8 = 0 (residual slot)
    }
    __syncwarp();
    for (int idx = lane; idx < 272; idx += 32) {
        int m = idx / 17;
        int w = idx - m * 17;
        float v = w_weights[(size_t)p * 272 + idx];
        // slot: wp = w&1 ; s = w>>1  (w=16 -> wp0 s8)
        ww_s[m * WWM + (w & 1) * 12 + (w >> 1)] = (nb_s[m] == P_) ? 0.0f : v;
    }
    __syncthreads();

    // lane = bg*16 + wp*8 + ih
    const int bg = (lane >> 4) & 1;
    const int wp = (lane >> 3) & 1;
    const int ih = lane & 7;

    // 4 batches per lane: b_j = bg + 2j
    const float* xb0 = in_pc + (size_t)(bg + 0) * P_ * CI_ + 2 * ih;
    const float* xb1 = in_pc + (size_t)(bg + 2) * P_ * CI_ + 2 * ih;
    const float* xb2 = in_pc + (size_t)(bg + 4) * P_ * CI_ + 2 * ih;
    const float* xb3 = in_pc + (size_t)(bg + 6) * P_ * CI_ + 2 * ih;

    // gacc2[s][j]: packed ch-pair accumulators. s=0..7: w=2s+wp ;
    // s=8: wp0 -> w=16 conv ; wp1 -> own-x (residual input, preserved by ww=0)
    ull gacc2[9][4];
    #pragma unroll
    for (int s = 0; s < 9; s++) {
        gacc2[s][0] = 0ull; gacc2[s][1] = 0ull;
        gacc2[s][2] = 0ull; gacc2[s][3] = 0ull;
    }
    if (wp) {
        size_t po = (size_t)p * CI_;
        gacc2[8][0] = *(const ull*)(xb0 + po);
        gacc2[8][1] = *(const ull*)(xb1 + po);
        gacc2[8][2] = *(const ull*)(xb2 + po);
        gacc2[8][3] = *(const ull*)(xb3 + po);
    }

    // ---- stage A ----
    const float* wwp = ww_s + wp * 12;
    #pragma unroll 4
    for (int m = 0; m < M_; m++) {
        int nb  = nb_s[m];
        int nbc = (nb == P_) ? 0 : nb;          // ww zeroed for pad
        size_t xo = (size_t)nbc * CI_;
        ull x0 = *(const ull*)(xb0 + xo);
        ull x1 = *(const ull*)(xb1 + xo);
        ull x2 = *(const ull*)(xb2 + xo);
        ull x3 = *(const ull*)(xb3 + xo);
        const float* wm = wwp + m * WWM;
        float4 fA = *(const float4*)(wm);
        float4 fB = *(const float4*)(wm + 4);
        float  f8 = wm[8];
        float fs[9] = {fA.x, fA.y, fA.z, fA.w, fB.x, fB.y, fB.z, fB.w, f8};
        #pragma unroll
        for (int s = 0; s < 9; s++) {
            ull f2;
            uint32_t fb = __float_as_uint(fs[s]);
            PACK_REPL_F32X2(f2, fb);
            FMA_F32X2(gacc2[s][0], f2, x0, gacc2[s][0]);
            FMA_F32X2(gacc2[s][1], f2, x1, gacc2[s][1]);
            FMA_F32X2(gacc2[s][2], f2, x2, gacc2[s][2]);
            FMA_F32X2(gacc2[s][3], f2, x3, gacc2[s][3]);
        }
    }

    // ---- stage B: per o, 9 LDS.64 of Wf, each feeding 4 FFMA2 ----
    const float* wfih = Wf + 2 * ih;
    const int h2 = (lane >> 2) & 1;
    const int h1 = (lane >> 1) & 1;
    const int jfin   = h2 * 2 + h1;
    const int batchf = bg + 2 * jfin;
    float* outbase = out + ((size_t)batchf * P_ + p) * CO_;

    #pragma unroll 1
    for (int t = 0; t < 16; t++) {
        float a_s[2][4], r_s[2][4];

        #pragma unroll
        for (int oi = 0; oi < 2; oi++) {
            const int o = 2 * t + oi;
            const float* wfo = wfih + o * OSTRIDE;

            ull acc2[4] = {0ull, 0ull, 0ull, 0ull};
            #pragma unroll
            for (int s = 0; s < 8; s++) {
                ull wv = *(const ull*)(wfo + (2 * s + wp) * 16);
                FMA_F32X2(acc2[0], wv, gacc2[s][0], acc2[0]);
                FMA_F32X2(acc2[1], wv, gacc2[s][1], acc2[1]);
                FMA_F32X2(acc2[2], wv, gacc2[s][2], acc2[2]);
                FMA_F32X2(acc2[3], wv, gacc2[s][3], acc2[3]);
            }
            // slot 8: wp0 -> conv w=16 (offset 256) ; wp1 -> residual (offset 272)
            ull wv8 = *(const ull*)(wfo + (16 + wp) * 16);
            ull rt2[4] = {0ull, 0ull, 0ull, 0ull};
            if (wp == 0) {
                FMA_F32X2(acc2[0], wv8, gacc2[8][0], acc2[0]);
                FMA_F32X2(acc2[1], wv8, gacc2[8][1], acc2[1]);
                FMA_F32X2(acc2[2], wv8, gacc2[8][2], acc2[2]);
                FMA_F32X2(acc2[3], wv8, gacc2[8][3], acc2[3]);
            } else {
                MUL_F32X2(rt2[0], wv8, gacc2[8][0]);
                MUL_F32X2(rt2[1], wv8, gacc2[8][1]);
                MUL_F32X2(rt2[2], wv8, gacc2[8][2]);
                MUL_F32X2(rt2[3], wv8, gacc2[8][3]);
            }
            #pragma unroll
            for (int j = 0; j < 4; j++) {
                uint32_t lo, hi;
                UNPACK_F32X2(lo, hi, acc2[j]);
                a_s[oi][j] = __uint_as_float(lo) + __uint_as_float(hi);
                UNPACK_F32X2(lo, hi, rt2[j]);
                r_s[oi][j] = __uint_as_float(lo) + __uint_as_float(hi);
            }
        }

        // ---- reduce-scatter over 16 lanes (bits 3..0 = wp, h2, h1, bit0) ----
        float va1[4], vr1[4];
        #pragma unroll
        for (int c = 0; c < 4; c++) {
            float ka = wp ? a_s[1][c] : a_s[0][c];
            float sa = wp ? a_s[0][c] : a_s[1][c];
            va1[c] = ka + __shfl_xor_sync(0xffffffffu, sa, 8);
            float kr = wp ? r_s[1][c] : r_s[0][c];
            float sr = wp ? r_s[0][c] : r_s[1][c];
            vr1[c] = kr + __shfl_xor_sync(0xffffffffu, sr, 8);
        }
        float va2[2], vr2[2];
        #pragma unroll
        for (int c = 0; c < 2; c++) {
            float ka = h2 ? va1[2 + c] : va1[c];
            float sa = h2 ? va1[c]     : va1[2 + c];
            va2[c] = ka + __shfl_xor_sync(0xffffffffu, sa, 4);
            float kr = h2 ? vr1[2 + c] : vr1[c];
            float sr = h2 ? vr1[c]     : vr1[2 + c];
            vr2[c] = kr + __shfl_xor_sync(0xffffffffu, sr, 4);
        }
        float va3, vr3;
        {
            float ka = h1 ? va2[1] : va2[0];
            float sa = h1 ? va2[0] : va2[1];
            va3 = ka + __shfl_xor_sync(0xffffffffu, sa, 2);
            float kr = h1 ? vr2[1] : vr2[0];
            float sr = h1 ? vr2[0] : vr2[1];
            vr3 = kr + __shfl_xor_sync(0xffffffffu, sr, 2);
        }
        va3 += __shfl_xor_sync(0xffffffffu, va3, 1);
        vr3 += __shfl_xor_sync(0xffffffffu, vr3, 1);

        // ---- epilogue: lane (bit0==0) owns (o = 2t+wp, batch = bg+2*jfin) ----
        if ((lane & 1) == 0) {
            const int o = 2 * t + wp;
            float bi = bias[(size_t)p * CO_ + o];
            float c = va3 + bi;
            float e = (c > 0.0f) ? c : expm1f(c);
            outbase[o] = e * SQ_CONV + vr3 * SQ_RES;
        }
    }
}

extern "C" void kernel_launch(void* const* d_in, const int* in_sizes, int n_in,
                              void* d_out, int out_size)
{
    const float* in_pc       = nullptr;
    const float* weights     = nullptr;
    const float* bias        = nullptr;
    const float* w_weights   = nullptr;
    const float* weight_res  = nullptr;
    const int*   neighbor_id = nullptr;

    for (int i = 0; i < n_in; i++) {
        switch (in_sizes[i]) {
            case 2097152: in_pc       = (const float*)d_in[i]; break; // (8,16384,16)
            case 8704:    weights     = (const float*)d_in[i]; break; // (17,512)
            case 524288:  bias        = (const float*)d_in[i]; break; // (16384,32)
            case 4456448: w_weights   = (const float*)d_in[i]; break; // (16384,16,17)
            case 512:     weight_res  = (const float*)d_in[i]; break; // (32,16)
            case 262144:  neighbor_id = (const int*)d_in[i];   break; // (16384,16)
            default: break;
        }
    }

    const int smem_bytes = (32 * OSTRIDE + 4 * WARP_SM) * 4; // 43264
    cudaFuncSetAttribute(fused_conv_kernel,
                         cudaFuncAttributeMaxDynamicSharedMemorySize, smem_bytes);

    fused_conv_kernel<<<P_ / 4, 128, smem_bytes>>>(
        in_pc, weights, bias, w_weights, weight_res, neighbor_id, (float*)d_out);
}